// round 7
// baseline (speedup 1.0000x reference)
#include <cuda_runtime.h>

// LocalCosineSimilarity — warp-autonomous streaming box filter, v2.
// Horizontal 11-tap via direct 5-shuffle window tree (no prefix, no predication).
// Two rows per iteration (6 independent shuffle chains for ILP).
// Vertical 11-tap via per-lane smem ring + register running sums.

#define IMG_W  1024
#define IMG_H  1024
#define KW     11
#define HALO   5
#define WCOLS  22                 // output cols per warp (lanes 0..21)
#define NWARP  2
#define NT     (NWARP * 32)       // 64
#define CTAC   (NWARP * WCOLS)    // 44 output cols per CTA
#define CH     64                 // output rows per CTA
#define NR     (CH + 2 * HALO)    // 74 input rows (even)

__global__ void __launch_bounds__(NT, 16)
lcs_warp2_kernel(const float* __restrict__ xg, const float* __restrict__ yg,
                 float* __restrict__ outg)
{
    __shared__ float ring[KW][3][CTAC];   // 5.8 KB; each lane owns one column

    const int tid  = threadIdx.x;
    const int lane = tid & 31;
    const int w    = tid >> 5;

    const int base = blockIdx.x * CTAC + w * WCOLS;  // first output col of warp
    const int gy0  = blockIdx.y * CH;
    const int b    = blockIdx.z;

    const size_t HW = (size_t)IMG_W * IMG_H;
    const float* xb = xg + (size_t)b * 3 * HW;
    const float* yb = yg + (size_t)b * 3 * HW;
    float* outb = outg + (size_t)b * HW;

    const int  c_in   = base - HALO + lane;              // col this lane loads
    const bool colv   = (unsigned)c_in < (unsigned)IMG_W;
    const int  c_out  = base + lane;                     // col this lane outputs
    const bool active = (lane < WCOLS) && ((unsigned)c_out < (unsigned)IMG_W);
    const int  rcol   = w * WCOLS + lane;                // ring column (lane<WCOLS)

    for (int i = tid; i < KW * 3 * CTAC; i += NT)
        ((float*)ring)[i] = 0.f;
    __syncthreads();   // only barrier

    const float* xp = xb + (colv ? c_in : 0);
    const float* yp = yb + (colv ? c_in : 0);

    // channel-reduced products of one input row
    auto loadrow = [&](int r, float& pxx, float& pyy, float& pxy) {
        pxx = pyy = pxy = 0.f;
        const int gy = gy0 - HALO + r;
        if (r < NR && colv && (unsigned)gy < (unsigned)IMG_H) {
            const size_t o = (size_t)gy * IMG_W;
            #pragma unroll
            for (int ch = 0; ch < 3; ++ch) {
                const float xv = __ldg(xp + (size_t)ch * HW + o);
                const float yv = __ldg(yp + (size_t)ch * HW + o);
                pxx = fmaf(xv, xv, pxx);
                pyy = fmaf(yv, yv, pyy);
                pxy = fmaf(xv, yv, pxy);
            }
        }
    };

    // h[l] = v[l] + v[l+1] + ... + v[l+10]   (valid for lanes 0..21)
    auto wsum = [](float v) {
        const float a = v + __shfl_down_sync(0xffffffffu, v, 1);   // pairs
        const float t = a + __shfl_down_sync(0xffffffffu, a, 2);   // quads
        const float c = t + __shfl_down_sync(0xffffffffu, t, 4);   // sum of 8
        return c + __shfl_down_sync(0xffffffffu, a, 8)             // v[l+8..l+9]
                 + __shfl_down_sync(0xffffffffu, v, 10);           // v[l+10]
    };

    float n0xx, n0yy, n0xy, n1xx, n1yy, n1xy;
    loadrow(0, n0xx, n0yy, n0xy);
    loadrow(1, n1xx, n1yy, n1xy);

    float sxx = 0.f, syy = 0.f, sxy = 0.f;
    int slot0 = 0;

    #pragma unroll 1
    for (int r = 0; r < NR; r += 2) {
        const float p0xx = n0xx, p0yy = n0yy, p0xy = n0xy;
        const float p1xx = n1xx, p1yy = n1yy, p1xy = n1xy;

        // prefetch next row pair (overlaps the shuffle trees)
        loadrow(r + 2, n0xx, n0yy, n0xy);
        loadrow(r + 3, n1xx, n1yy, n1xy);

        // 6 independent horizontal window sums
        const float h0xx = wsum(p0xx), h0yy = wsum(p0yy), h0xy = wsum(p0xy);
        const float h1xx = wsum(p1xx), h1yy = wsum(p1yy), h1xy = wsum(p1xy);

        int slot1 = slot0 + 1; if (slot1 == KW) slot1 = 0;

        if (active) {
            // row r
            sxx += h0xx - ring[slot0][0][rcol];  ring[slot0][0][rcol] = h0xx;
            syy += h0yy - ring[slot0][1][rcol];  ring[slot0][1][rcol] = h0yy;
            sxy += h0xy - ring[slot0][2][rcol];  ring[slot0][2][rcol] = h0xy;
            if (r >= 2 * HALO) {
                const int ro = gy0 + r - 2 * HALO;
                outb[(size_t)ro * IMG_W + c_out] =
                    sxy / (sqrtf(sxx) * sqrtf(syy) + 1e-6f);
            }
            // row r+1
            sxx += h1xx - ring[slot1][0][rcol];  ring[slot1][0][rcol] = h1xx;
            syy += h1yy - ring[slot1][1][rcol];  ring[slot1][1][rcol] = h1yy;
            sxy += h1xy - ring[slot1][2][rcol];  ring[slot1][2][rcol] = h1xy;
            if (r + 1 >= 2 * HALO) {
                const int ro = gy0 + r + 1 - 2 * HALO;
                outb[(size_t)ro * IMG_W + c_out] =
                    sxy / (sqrtf(sxx) * sqrtf(syy) + 1e-6f);
            }
        }
        slot0 += 2; if (slot0 >= KW) slot0 -= KW;
    }
}

extern "C" void kernel_launch(void* const* d_in, const int* in_sizes, int n_in,
                              void* d_out, int out_size)
{
    const float* x = (const float*)d_in[0];
    const float* y = (const float*)d_in[1];
    float* out = (float*)d_out;

    dim3 grid((IMG_W + CTAC - 1) / CTAC,   // 24
              IMG_H / CH,                  // 16
              8);                          // batch -> 3072 CTAs
    lcs_warp2_kernel<<<grid, NT>>>(x, y, out);
}

// round 13
// speedup vs baseline: 1.5989x; 1.5989x over previous
#include <cuda_runtime.h>

// LocalCosineSimilarity — warp-autonomous streaming box filter, v3 (re-bench).
// R6 structure (4 warps/CTA, CH=64, 1-row prefetch pipeline) with the
// horizontal 11-tap done as a direct 5-shuffle window tree (no prefix scan,
// no predicated adds): h[l] = sum v[l..l+10].

#define IMG_W  1024
#define IMG_H  1024
#define KW     11
#define HALO   5
#define WCOLS  22                 // output cols per warp (lanes 0..21)
#define NWARP  4
#define NT     (NWARP * 32)       // 128
#define CTAC   (NWARP * WCOLS)    // 88 output cols per CTA
#define CH     64                 // output rows per CTA
#define NR     (CH + 2 * HALO)    // 74 input rows streamed

__global__ void __launch_bounds__(NT, 8)
lcs_warp3_kernel(const float* __restrict__ xg, const float* __restrict__ yg,
                 float* __restrict__ outg)
{
    __shared__ float ring[KW][3][CTAC];   // 11.6 KB; each lane owns one column

    const int tid  = threadIdx.x;
    const int lane = tid & 31;
    const int w    = tid >> 5;

    const int base = blockIdx.x * CTAC + w * WCOLS;   // first output col of warp
    const int gy0  = blockIdx.y * CH;
    const int b    = blockIdx.z;

    const size_t HW = (size_t)IMG_W * IMG_H;
    const float* xb = xg + (size_t)b * 3 * HW;
    const float* yb = yg + (size_t)b * 3 * HW;
    float* outb = outg + (size_t)b * HW;

    const int  c_in   = base - HALO + lane;            // col this lane loads
    const bool colv   = (unsigned)c_in < (unsigned)IMG_W;
    const int  c_out  = base + lane;                   // col this lane outputs
    const bool active = (lane < WCOLS) && ((unsigned)c_out < (unsigned)IMG_W);
    const int  rcol   = w * WCOLS + lane;              // ring column (lane<WCOLS)

    // zero the ring (each lane only touches its own column afterwards)
    for (int i = tid; i < KW * 3 * CTAC; i += NT)
        ((float*)ring)[i] = 0.f;
    __syncthreads();   // only barrier in the kernel

    const float* xp = xb + (colv ? c_in : 0);
    const float* yp = yb + (colv ? c_in : 0);

    // ---- prefetch row 0 products ----
    float nxx, nyy, nxy;
    {
        const int gy = gy0 - HALO;
        nxx = nyy = nxy = 0.f;
        if (colv && (unsigned)gy < (unsigned)IMG_H) {
            const size_t o = (size_t)gy * IMG_W;
            #pragma unroll
            for (int ch = 0; ch < 3; ++ch) {
                const float xv = __ldg(xp + (size_t)ch * HW + o);
                const float yv = __ldg(yp + (size_t)ch * HW + o);
                nxx = fmaf(xv, xv, nxx);
                nyy = fmaf(yv, yv, nyy);
                nxy = fmaf(xv, yv, nxy);
            }
        }
    }

    float sxx = 0.f, syy = 0.f, sxy = 0.f;
    int slot = 0;

    #pragma unroll 2
    for (int r = 0; r < NR; ++r) {
        // consume prefetched row r
        const float pxx = nxx, pyy = nyy, pxy = nxy;

        // ---- prefetch row r+1 (overlaps the shuffle trees) ----
        nxx = nyy = nxy = 0.f;
        {
            const int gy = gy0 - HALO + r + 1;
            if ((r + 1 < NR) && colv && (unsigned)gy < (unsigned)IMG_H) {
                const size_t o = (size_t)gy * IMG_W;
                #pragma unroll
                for (int ch = 0; ch < 3; ++ch) {
                    const float xv = __ldg(xp + (size_t)ch * HW + o);
                    const float yv = __ldg(yp + (size_t)ch * HW + o);
                    nxx = fmaf(xv, xv, nxx);
                    nyy = fmaf(yv, yv, nyy);
                    nxy = fmaf(xv, yv, nxy);
                }
            }
        }

        // ---- horizontal 11-tap window tree: h[l] = sum v[l..l+10] ----
        // a = v+v>>1 (2-sums), t = a+a>>2 (4-sums), c = t+t>>4 (8-sums),
        // h = c + a>>8 + v>>10.  3 independent chains for ILP.
        const float a0 = pxx + __shfl_down_sync(0xffffffffu, pxx, 1);
        const float a1 = pyy + __shfl_down_sync(0xffffffffu, pyy, 1);
        const float a2 = pxy + __shfl_down_sync(0xffffffffu, pxy, 1);
        const float t0 = a0 + __shfl_down_sync(0xffffffffu, a0, 2);
        const float t1 = a1 + __shfl_down_sync(0xffffffffu, a1, 2);
        const float t2 = a2 + __shfl_down_sync(0xffffffffu, a2, 2);
        const float c0 = t0 + __shfl_down_sync(0xffffffffu, t0, 4);
        const float c1 = t1 + __shfl_down_sync(0xffffffffu, t1, 4);
        const float c2 = t2 + __shfl_down_sync(0xffffffffu, t2, 4);
        const float hxx = c0 + __shfl_down_sync(0xffffffffu, a0, 8)
                             + __shfl_down_sync(0xffffffffu, pxx, 10);
        const float hyy = c1 + __shfl_down_sync(0xffffffffu, a1, 8)
                             + __shfl_down_sync(0xffffffffu, pyy, 10);
        const float hxy = c2 + __shfl_down_sync(0xffffffffu, a2, 8)
                             + __shfl_down_sync(0xffffffffu, pxy, 10);

        // ---- vertical sliding window + finalize ----
        if (active) {
            sxx += hxx - ring[slot][0][rcol];  ring[slot][0][rcol] = hxx;
            syy += hyy - ring[slot][1][rcol];  ring[slot][1][rcol] = hyy;
            sxy += hxy - ring[slot][2][rcol];  ring[slot][2][rcol] = hxy;

            if (r >= 2 * HALO) {
                const int ro = gy0 + r - 2 * HALO;
                outb[(size_t)ro * IMG_W + c_out] =
                    sxy / (sqrtf(sxx) * sqrtf(syy) + 1e-6f);
            }
        }
        if (++slot == KW) slot = 0;
    }
}

extern "C" void kernel_launch(void* const* d_in, const int* in_sizes, int n_in,
                              void* d_out, int out_size)
{
    const float* x = (const float*)d_in[0];
    const float* y = (const float*)d_in[1];
    float* out = (float*)d_out;

    dim3 grid((IMG_W + CTAC - 1) / CTAC,   // 12
              IMG_H / CH,                  // 16
              8);                          // batch -> 1536 CTAs
    lcs_warp3_kernel<<<grid, NT>>>(x, y, out);
}